// round 5
// baseline (speedup 1.0000x reference)
#include <cuda_runtime.h>
#include <cuda_bf16.h>

// Problem constants (match reference)
#define BB   64
#define CC   2
#define LL   64
#define NBIN 16
#define NVOX (LL*LL*LL)        // 262144
#define NPAIR (BB*CC)          // 128
#define NDENSE 25              // only ax,az in 0..4 ever occur
#define DSTRIDE 32             // padded scratch stride per pair
#define EPSV 1e-5f

// tan^2(22a degrees), a = 1..4 (double-accurate, stored f32)
#define T1Q 0.16323719f
#define T2Q 0.93255481f
#define T3Q 5.0446812f
#define T4Q 820.03500f

// Scratch (no allocations allowed)
__device__ unsigned char g_bins[NVOX];            // DENSE bin id: ax*5+az in 0..24
__device__ float g_scratch[NPAIR*DSTRIDE];        // per-(b,c) dense bin sums

// ---------------------------------------------------------------------------
// Kernel A: voxel -> dense bin table via monotone threshold counting
//   ax = #{a : j^2+k^2 >= i^2 tan^2(22a)},  az = #{a : k^2 >= (i^2+j^2) tan^2(22a)}
// (equivalent to floor(atan2(...)*180/pi/22); only v=0 differs, where mag=0).
// Also zeroes the scatter scratch.
// ---------------------------------------------------------------------------
__global__ __launch_bounds__(256) void build_tables_kernel() {
    int v = blockIdx.x * blockDim.x + threadIdx.x;
    if (v < NVOX) {
        float fi = (float)(v >> 12);
        float fj = (float)((v >> 6) & 63);
        float fk = (float)(v & 63);
        float ii = fi * fi;
        float jj = fj * fj;
        float kk = fk * fk;
        float jk = jj + kk;        // xc^2
        float ij = ii + jj;        // zc^2
        int ax = (jk >= ii * T1Q) + (jk >= ii * T2Q)
               + (jk >= ii * T3Q) + (jk >= ii * T4Q);
        int az = (kk >= ij * T1Q) + (kk >= ij * T2Q)
               + (kk >= ij * T3Q) + (kk >= ij * T4Q);
        g_bins[v] = (unsigned char)(ax * 5 + az);
    }
    if (v < NPAIR * DSTRIDE) g_scratch[v] = 0.0f;
}

// ---------------------------------------------------------------------------
// Kernel B: streaming weighted histogram, branchless, 16 elements per
// thread-iteration (4x LDG.128 of x + 1x LDG.128 of 16 bin bytes).
//   - per-thread private histogram column hist[bin*256 + t]: bank = t mod 32,
//     conflict-free for any cross-lane bin pattern
//   - mag recomputed inline with __fsqrt_rn (bit-exact vs reference)
//   - block flush: tree-reduce + 25 global atomics per block
// ---------------------------------------------------------------------------
#define SPLIT 16                       // blocks per (b,c) pair
#define CHUNK (NVOX / SPLIT)           // 16384 elements
#define BTHREADS 256

__global__ __launch_bounds__(BTHREADS, 4) void accumulate_kernel(const float* __restrict__ x) {
    __shared__ float hist[NDENSE * BTHREADS];     // 25.6 KB
    const int t = threadIdx.x;
    #pragma unroll
    for (int i = 0; i < NDENSE; i++) hist[i * BTHREADS + t] = 0.0f;
    // each thread touches only column t -> no sync needed before the loop

    const int pair  = blockIdx.x >> 4;            // b*C + c
    const int part  = blockIdx.x & (SPLIT - 1);
    const int vbase = part * CHUNK;
    const float* __restrict__ xp = x + (size_t)pair * NVOX + vbase;
    const unsigned char* __restrict__ bp = g_bins + vbase;

    // CHUNK/(256*16) = 4 iterations
    #pragma unroll 2
    for (int off = t * 16; off < CHUNK; off += BTHREADS * 16) {
        float4 x0 = *reinterpret_cast<const float4*>(xp + off);
        float4 x1 = *reinterpret_cast<const float4*>(xp + off + 4);
        float4 x2 = *reinterpret_cast<const float4*>(xp + off + 8);
        float4 x3 = *reinterpret_cast<const float4*>(xp + off + 12);
        uint4  bq = *reinterpret_cast<const uint4*>(bp + off);

        int v = vbase + off;                      // off%16==0 -> k..k+15 in-row
        float fi = (float)(v >> 12);
        float fj = (float)((v >> 6) & 63);
        float fk = (float)(v & 63);
        float s2 = fi * fi + fj * fj;

        // group 0: elems 0..3
        {
            float m0 = __fsqrt_rn(s2 + fk*fk);
            float m1 = __fsqrt_rn(s2 + (fk+1.0f)*(fk+1.0f));
            float m2 = __fsqrt_rn(s2 + (fk+2.0f)*(fk+2.0f));
            float m3 = __fsqrt_rn(s2 + (fk+3.0f)*(fk+3.0f));
            unsigned w = bq.x;
            hist[(( w        & 0xffu) << 8) + t] += x0.x * m0;
            hist[(((w >>  8) & 0xffu) << 8) + t] += x0.y * m1;
            hist[(((w >> 16) & 0xffu) << 8) + t] += x0.z * m2;
            hist[(( w >> 24         ) << 8) + t] += x0.w * m3;
        }
        // group 1: elems 4..7
        {
            float m0 = __fsqrt_rn(s2 + (fk+4.0f)*(fk+4.0f));
            float m1 = __fsqrt_rn(s2 + (fk+5.0f)*(fk+5.0f));
            float m2 = __fsqrt_rn(s2 + (fk+6.0f)*(fk+6.0f));
            float m3 = __fsqrt_rn(s2 + (fk+7.0f)*(fk+7.0f));
            unsigned w = bq.y;
            hist[(( w        & 0xffu) << 8) + t] += x1.x * m0;
            hist[(((w >>  8) & 0xffu) << 8) + t] += x1.y * m1;
            hist[(((w >> 16) & 0xffu) << 8) + t] += x1.z * m2;
            hist[(( w >> 24         ) << 8) + t] += x1.w * m3;
        }
        // group 2: elems 8..11
        {
            float m0 = __fsqrt_rn(s2 + (fk+ 8.0f)*(fk+ 8.0f));
            float m1 = __fsqrt_rn(s2 + (fk+ 9.0f)*(fk+ 9.0f));
            float m2 = __fsqrt_rn(s2 + (fk+10.0f)*(fk+10.0f));
            float m3 = __fsqrt_rn(s2 + (fk+11.0f)*(fk+11.0f));
            unsigned w = bq.z;
            hist[(( w        & 0xffu) << 8) + t] += x2.x * m0;
            hist[(((w >>  8) & 0xffu) << 8) + t] += x2.y * m1;
            hist[(((w >> 16) & 0xffu) << 8) + t] += x2.z * m2;
            hist[(( w >> 24         ) << 8) + t] += x2.w * m3;
        }
        // group 3: elems 12..15
        {
            float m0 = __fsqrt_rn(s2 + (fk+12.0f)*(fk+12.0f));
            float m1 = __fsqrt_rn(s2 + (fk+13.0f)*(fk+13.0f));
            float m2 = __fsqrt_rn(s2 + (fk+14.0f)*(fk+14.0f));
            float m3 = __fsqrt_rn(s2 + (fk+15.0f)*(fk+15.0f));
            unsigned w = bq.w;
            hist[(( w        & 0xffu) << 8) + t] += x3.x * m0;
            hist[(((w >>  8) & 0xffu) << 8) + t] += x3.y * m1;
            hist[(((w >> 16) & 0xffu) << 8) + t] += x3.z * m2;
            hist[(( w >> 24         ) << 8) + t] += x3.w * m3;
        }
    }

    __syncthreads();

    // Flush: 8 warps; warp w handles bins {w, w+8, w+16, w+24}
    const int warp = t >> 5, lane = t & 31;
    const unsigned full = 0xffffffffu;
    for (int bin = warp; bin < NDENSE; bin += 8) {
        const float* row = &hist[bin * BTHREADS];
        float s = 0.0f;
        #pragma unroll
        for (int j = 0; j < 8; j++) s += row[lane + 32*j];
        #pragma unroll
        for (int d = 16; d; d >>= 1) s += __shfl_down_sync(full, s, d);
        if (lane == 0) atomicAdd(&g_scratch[pair * DSTRIDE + bin], s);
    }
}

// ---------------------------------------------------------------------------
// Kernel C: per-channel group norm over (B, 16, 16) = 16384 values; only
// 64*25 dense entries can be nonzero. Two-pass mean/var; zero bins enter the
// variance analytically as (16384 - 64*25) * mean^2. One block per channel.
// ---------------------------------------------------------------------------
__global__ __launch_bounds__(256) void gn_kernel(const float* __restrict__ gamma,
                                                 const float* __restrict__ beta,
                                                 float* __restrict__ out) {
    const int c = blockIdx.x;
    const int t = threadIdx.x;
    const int lane = t & 31, warp = t >> 5;
    const unsigned full = 0xffffffffu;

    __shared__ float red[8];
    __shared__ float s_mean, s_rs;

    float vals[7];                      // ceil(1600/256) = 7 slots
    float sum = 0.0f;
    #pragma unroll
    for (int i = 0; i < 7; i++) {
        int idx = i * 256 + t;
        float g = 0.0f;
        if (idx < BB * NDENSE) {
            int b = idx / NDENSE, d = idx % NDENSE;
            g = g_scratch[(b * CC + c) * DSTRIDE + d];
        }
        vals[i] = g;
        sum += g;
    }
    #pragma unroll
    for (int d = 16; d; d >>= 1) sum += __shfl_down_sync(full, sum, d);
    if (lane == 0) red[warp] = sum;
    __syncthreads();
    if (t == 0) {
        float tot = 0.0f;
        #pragma unroll
        for (int w = 0; w < 8; w++) tot += red[w];
        s_mean = tot * (1.0f / (BB * NBIN * NBIN));
    }
    __syncthreads();
    float mean = s_mean;

    float vs = 0.0f;
    #pragma unroll
    for (int i = 0; i < 7; i++) {
        int idx = i * 256 + t;
        if (idx < BB * NDENSE) {
            float d = vals[i] - mean;
            vs = fmaf(d, d, vs);
        }
    }
    #pragma unroll
    for (int d = 16; d; d >>= 1) vs += __shfl_down_sync(full, vs, d);
    __syncthreads();
    if (lane == 0) red[warp] = vs;
    __syncthreads();
    if (t == 0) {
        float tot = 0.0f;
        #pragma unroll
        for (int w = 0; w < 8; w++) tot += red[w];
        tot += (float)(BB * NBIN * NBIN - BB * NDENSE) * s_mean * s_mean;
        float var = tot * (1.0f / (BB * NBIN * NBIN));
        s_rs = rsqrtf(var + EPSV);
    }
    __syncthreads();
    float rs = s_rs;
    float ga = gamma[c], be = beta[c];

    for (int idx = t; idx < BB * NBIN * NBIN; idx += 256) {
        int b = idx >> 8, s = idx & 255;
        int ax = s >> 4, az = s & 15;
        float g = 0.0f;
        if (ax < 5 && az < 5)
            g = g_scratch[(b * CC + c) * DSTRIDE + ax * 5 + az];
        out[(b * CC + c) * 256 + s] = (g - mean) * rs * ga + be;
    }
}

// ---------------------------------------------------------------------------
extern "C" void kernel_launch(void* const* d_in, const int* in_sizes, int n_in,
                              void* d_out, int out_size) {
    const float* x     = (const float*)d_in[0];   // [64, 2*64^3]
    const float* gamma = (const float*)d_in[1];   // [2]
    const float* beta  = (const float*)d_in[2];   // [2]
    float* out = (float*)d_out;                   // [64,2,16,16] f32

    build_tables_kernel<<<(NVOX + 255) / 256, 256>>>();
    accumulate_kernel<<<NPAIR * SPLIT, BTHREADS>>>(x);
    gn_kernel<<<CC, 256>>>(gamma, beta, out);
}

// round 6
// speedup vs baseline: 1.1992x; 1.1992x over previous
#include <cuda_runtime.h>
#include <cuda_bf16.h>

// Problem constants (match reference)
#define BB   64
#define CC   2
#define LL   64
#define NBIN 16
#define NVOX (LL*LL*LL)        // 262144
#define NPAIR (BB*CC)          // 128
#define NDENSE 25              // only ax,az in 0..4 ever occur
#define DSTRIDE 32             // padded scratch stride per pair
#define EPSV 1e-5f

// tan^2(22a degrees), a = 1..4 (double-accurate, stored f32)
#define T1Q 0.16323719f
#define T2Q 0.93255481f
#define T3Q 5.0446812f
#define T4Q 820.03500f

// Scratch (no allocations allowed)
__device__ unsigned char g_bins[NVOX];            // DENSE bin id: ax*5+az in 0..24
__device__ float g_scratch[NPAIR*DSTRIDE];        // per-(b,c) dense bin sums

// ---------------------------------------------------------------------------
// Kernel A: voxel -> dense bin table via monotone threshold counting
//   ax = #{a : j^2+k^2 >= i^2 tan^2(22a)},  az = #{a : k^2 >= (i^2+j^2) tan^2(22a)}
// (equivalent to floor(atan2(...)*180/pi/22); only v=0 differs, where mag=0).
// 4 voxels/thread, single uchar4 store -> 65k threads, overhead-minimal.
// Also zeroes the scatter scratch.
// ---------------------------------------------------------------------------
__global__ __launch_bounds__(256) void build_tables_kernel() {
    int q = blockIdx.x * blockDim.x + threadIdx.x;    // quad id, < NVOX/4
    int v = q * 4;
    float fi = (float)(v >> 12);
    float fj = (float)((v >> 6) & 63);
    float fk = (float)(v & 63);                       // k..k+3 in-row
    float ii = fi * fi;
    float jj = fj * fj;

    float a1 = ii * T1Q, a2 = ii * T2Q, a3 = ii * T3Q, a4 = ii * T4Q;
    float ij = ii + jj;
    float z1 = ij * T1Q, z2 = ij * T2Q, z3 = ij * T3Q, z4 = ij * T4Q;

    unsigned out = 0;
    #pragma unroll
    for (int u = 0; u < 4; u++) {
        float fku = fk + (float)u;
        float kk = fku * fku;
        float jk = jj + kk;
        int ax = (jk >= a1) + (jk >= a2) + (jk >= a3) + (jk >= a4);
        int az = (kk >= z1) + (kk >= z2) + (kk >= z3) + (kk >= z4);
        out |= (unsigned)(ax * 5 + az) << (8 * u);
    }
    *reinterpret_cast<unsigned*>(g_bins + v) = out;

    if (q < NPAIR * DSTRIDE) g_scratch[q] = 0.0f;
}

// ---------------------------------------------------------------------------
// Kernel B: streaming weighted histogram, fully BRANCHLESS hot loop.
//   - per-thread private histogram column: hist[bin*256 + t]
//     bank = t mod 32  ->  conflict-free for ANY bin pattern across lanes
//   - 8 elements per thread-iteration: 2x LDG.128 (__ldcs, streaming) + 1x
//     LDG.64 of 8 bin bytes (L2-resident table)
//   - mag recomputed inline with __fsqrt_rn (bit-exact vs reference)
//   - block flush: tree-reduce + 25 global atomics per block
// ---------------------------------------------------------------------------
#define SPLIT 16                       // blocks per (b,c) pair
#define CHUNK (NVOX / SPLIT)           // 16384 elements
#define BTHREADS 256

__global__ __launch_bounds__(BTHREADS) void accumulate_kernel(const float* __restrict__ x) {
    __shared__ float hist[NDENSE * BTHREADS];     // 25.6 KB
    const int t = threadIdx.x;
    #pragma unroll
    for (int i = 0; i < NDENSE; i++) hist[i * BTHREADS + t] = 0.0f;
    // each thread touches only column t -> no sync needed before the loop
    float* __restrict__ h = hist + t;

    const int pair  = blockIdx.x >> 4;            // b*C + c
    const int part  = blockIdx.x & (SPLIT - 1);
    const int vbase = part * CHUNK;
    const float* __restrict__ xp = x + (size_t)pair * NVOX + vbase;
    const unsigned char* __restrict__ bp = g_bins + vbase;

    #pragma unroll 2
    for (int off = t * 8; off < CHUNK; off += BTHREADS * 8) {
        float4 xa = __ldcs(reinterpret_cast<const float4*>(xp + off));
        float4 xb = __ldcs(reinterpret_cast<const float4*>(xp + off + 4));
        uint2  bq = *reinterpret_cast<const uint2*>(bp + off);

        int v = vbase + off;                      // off%8==0 -> k..k+7 in-row
        float fi = (float)(v >> 12);
        float fj = (float)((v >> 6) & 63);
        float fk = (float)(v & 63);
        float s2 = fi*fi + fj*fj;
        float m0 = __fsqrt_rn(s2 + fk*fk);
        float m1 = __fsqrt_rn(s2 + (fk+1.0f)*(fk+1.0f));
        float m2 = __fsqrt_rn(s2 + (fk+2.0f)*(fk+2.0f));
        float m3 = __fsqrt_rn(s2 + (fk+3.0f)*(fk+3.0f));
        float m4 = __fsqrt_rn(s2 + (fk+4.0f)*(fk+4.0f));
        float m5 = __fsqrt_rn(s2 + (fk+5.0f)*(fk+5.0f));
        float m6 = __fsqrt_rn(s2 + (fk+6.0f)*(fk+6.0f));
        float m7 = __fsqrt_rn(s2 + (fk+7.0f)*(fk+7.0f));

        // row offset = bin*256 = byte<<8; h = hist + t (private column)
        h[(( bq.x        & 0xffu) << 8)] += xa.x * m0;
        h[(((bq.x >>  8) & 0xffu) << 8)] += xa.y * m1;
        h[(((bq.x >> 16) & 0xffu) << 8)] += xa.z * m2;
        h[(( bq.x >> 24         ) << 8)] += xa.w * m3;
        h[(( bq.y        & 0xffu) << 8)] += xb.x * m4;
        h[(((bq.y >>  8) & 0xffu) << 8)] += xb.y * m5;
        h[(((bq.y >> 16) & 0xffu) << 8)] += xb.z * m6;
        h[(( bq.y >> 24         ) << 8)] += xb.w * m7;
    }

    __syncthreads();

    // Flush: 8 warps; warp w handles bins {w, w+8, w+16, w+24}
    const int warp = t >> 5, lane = t & 31;
    const unsigned full = 0xffffffffu;
    for (int bin = warp; bin < NDENSE; bin += 8) {
        const float* row = &hist[bin * BTHREADS];
        float s = 0.0f;
        #pragma unroll
        for (int j = 0; j < 8; j++) s += row[lane + 32*j];
        #pragma unroll
        for (int d = 16; d; d >>= 1) s += __shfl_down_sync(full, s, d);
        if (lane == 0) atomicAdd(&g_scratch[pair * DSTRIDE + bin], s);
    }
}

// ---------------------------------------------------------------------------
// Kernel C: per-channel group norm over (B, 16, 16) = 16384 values; only
// 64*25 dense entries can be nonzero. Two-pass mean/var; zero bins enter the
// variance analytically as (16384 - 64*25) * mean^2. One block per channel.
// ---------------------------------------------------------------------------
__global__ __launch_bounds__(256) void gn_kernel(const float* __restrict__ gamma,
                                                 const float* __restrict__ beta,
                                                 float* __restrict__ out) {
    const int c = blockIdx.x;
    const int t = threadIdx.x;
    const int lane = t & 31, warp = t >> 5;
    const unsigned full = 0xffffffffu;

    __shared__ float red[8];
    __shared__ float s_mean, s_rs;

    float vals[7];                      // ceil(1600/256) = 7 slots
    float sum = 0.0f;
    #pragma unroll
    for (int i = 0; i < 7; i++) {
        int idx = i * 256 + t;
        float g = 0.0f;
        if (idx < BB * NDENSE) {
            int b = idx / NDENSE, d = idx % NDENSE;
            g = g_scratch[(b * CC + c) * DSTRIDE + d];
        }
        vals[i] = g;
        sum += g;
    }
    #pragma unroll
    for (int d = 16; d; d >>= 1) sum += __shfl_down_sync(full, sum, d);
    if (lane == 0) red[warp] = sum;
    __syncthreads();
    if (t == 0) {
        float tot = 0.0f;
        #pragma unroll
        for (int w = 0; w < 8; w++) tot += red[w];
        s_mean = tot * (1.0f / (BB * NBIN * NBIN));
    }
    __syncthreads();
    float mean = s_mean;

    float vs = 0.0f;
    #pragma unroll
    for (int i = 0; i < 7; i++) {
        int idx = i * 256 + t;
        if (idx < BB * NDENSE) {
            float d = vals[i] - mean;
            vs = fmaf(d, d, vs);
        }
    }
    #pragma unroll
    for (int d = 16; d; d >>= 1) vs += __shfl_down_sync(full, vs, d);
    __syncthreads();
    if (lane == 0) red[warp] = vs;
    __syncthreads();
    if (t == 0) {
        float tot = 0.0f;
        #pragma unroll
        for (int w = 0; w < 8; w++) tot += red[w];
        tot += (float)(BB * NBIN * NBIN - BB * NDENSE) * s_mean * s_mean;
        float var = tot * (1.0f / (BB * NBIN * NBIN));
        s_rs = rsqrtf(var + EPSV);
    }
    __syncthreads();
    float rs = s_rs;
    float ga = gamma[c], be = beta[c];

    for (int idx = t; idx < BB * NBIN * NBIN; idx += 256) {
        int b = idx >> 8, s = idx & 255;
        int ax = s >> 4, az = s & 15;
        float g = 0.0f;
        if (ax < 5 && az < 5)
            g = g_scratch[(b * CC + c) * DSTRIDE + ax * 5 + az];
        out[(b * CC + c) * 256 + s] = (g - mean) * rs * ga + be;
    }
}

// ---------------------------------------------------------------------------
extern "C" void kernel_launch(void* const* d_in, const int* in_sizes, int n_in,
                              void* d_out, int out_size) {
    const float* x     = (const float*)d_in[0];   // [64, 2*64^3]
    const float* gamma = (const float*)d_in[1];   // [2]
    const float* beta  = (const float*)d_in[2];   // [2]
    float* out = (float*)d_out;                   // [64,2,16,16] f32

    build_tables_kernel<<<NVOX / 4 / 256, 256>>>();
    accumulate_kernel<<<NPAIR * SPLIT, BTHREADS>>>(x);
    gn_kernel<<<CC, 256>>>(gamma, beta, out);
}

// round 7
// speedup vs baseline: 1.3324x; 1.1111x over previous
#include <cuda_runtime.h>
#include <cuda_bf16.h>

// Problem constants (match reference)
#define BB   64
#define CC   2
#define LL   64
#define NBIN 16
#define NVOX (LL*LL*LL)        // 262144
#define NPAIR (BB*CC)          // 128
#define NDENSE 25              // only ax,az in 0..4 ever occur
#define DSTRIDE 32             // padded scratch stride per pair
#define EPSV 1e-5f

// tan^2(22a degrees), a = 1..4 (double-accurate, stored f32)
#define T1Q 0.16323719f
#define T2Q 0.93255481f
#define T3Q 5.0446812f
#define T4Q 820.03500f

// Scratch (no allocations allowed)
__device__ unsigned char g_bins[NVOX];            // DENSE bin id: ax*5+az in 0..24
__device__ float g_scratch[NPAIR*DSTRIDE];        // per-(b,c) dense bin sums

// ---------------------------------------------------------------------------
// Kernel A: voxel -> dense bin table via monotone threshold counting
//   ax = #{a : j^2+k^2 >= i^2 tan^2(22a)},  az = #{a : k^2 >= (i^2+j^2) tan^2(22a)}
// (equivalent to floor(atan2(...)*180/pi/22); only v=0 differs, where mag=0).
// 4 voxels/thread, single uchar4 store. Also zeroes the scatter scratch.
// ---------------------------------------------------------------------------
__global__ __launch_bounds__(256) void build_tables_kernel() {
    int q = blockIdx.x * blockDim.x + threadIdx.x;    // quad id, < NVOX/4
    int v = q * 4;
    float fi = (float)(v >> 12);
    float fj = (float)((v >> 6) & 63);
    float fk = (float)(v & 63);                       // k..k+3 in-row
    float ii = fi * fi;
    float jj = fj * fj;

    float a1 = ii * T1Q, a2 = ii * T2Q, a3 = ii * T3Q, a4 = ii * T4Q;
    float ij = ii + jj;
    float z1 = ij * T1Q, z2 = ij * T2Q, z3 = ij * T3Q, z4 = ij * T4Q;

    unsigned out = 0;
    #pragma unroll
    for (int u = 0; u < 4; u++) {
        float fku = fk + (float)u;
        float kk = fku * fku;
        float jk = jj + kk;
        int ax = (jk >= a1) + (jk >= a2) + (jk >= a3) + (jk >= a4);
        int az = (kk >= z1) + (kk >= z2) + (kk >= z3) + (kk >= z4);
        out |= (unsigned)(ax * 5 + az) << (8 * u);
    }
    *reinterpret_cast<unsigned*>(g_bins + v) = out;

    if (q < NPAIR * DSTRIDE) g_scratch[q] = 0.0f;
}

// ---------------------------------------------------------------------------
// Kernel B: streaming weighted histogram, fully BRANCHLESS hot loop.
//   - per-thread private histogram column: hist[bin*256 + t]
//     bank = t mod 32  ->  conflict-free for ANY bin pattern across lanes
//   - 8 elements per thread-iteration: 2x LDG.128 (__ldcs, streaming) + 1x
//     LDG.64 of 8 bin bytes (L2-resident table)
//   - SPLIT=8 -> 1024 CTAs = ONE wave at 8 CTA/SM occupancy (no wave
//     quantization), 16 loop iterations for deep steady state
//   - mag recomputed inline with __fsqrt_rn (bit-exact vs reference)
//   - block flush: tree-reduce + 25 global atomics per block
// ---------------------------------------------------------------------------
#define SPLIT 8                        // blocks per (b,c) pair
#define CHUNK (NVOX / SPLIT)           // 32768 elements
#define BTHREADS 256

__global__ __launch_bounds__(BTHREADS) void accumulate_kernel(const float* __restrict__ x) {
    __shared__ float hist[NDENSE * BTHREADS];     // 25.6 KB
    const int t = threadIdx.x;
    #pragma unroll
    for (int i = 0; i < NDENSE; i++) hist[i * BTHREADS + t] = 0.0f;
    // each thread touches only column t -> no sync needed before the loop
    float* __restrict__ h = hist + t;

    const int pair  = blockIdx.x >> 3;            // b*C + c
    const int part  = blockIdx.x & (SPLIT - 1);
    const int vbase = part * CHUNK;
    const float* __restrict__ xp = x + (size_t)pair * NVOX + vbase;
    const unsigned char* __restrict__ bp = g_bins + vbase;

    // CHUNK/(256*8) = 16 iterations
    #pragma unroll 4
    for (int off = t * 8; off < CHUNK; off += BTHREADS * 8) {
        float4 xa = __ldcs(reinterpret_cast<const float4*>(xp + off));
        float4 xb = __ldcs(reinterpret_cast<const float4*>(xp + off + 4));
        uint2  bq = *reinterpret_cast<const uint2*>(bp + off);

        int v = vbase + off;                      // off%8==0 -> k..k+7 in-row
        float fi = (float)(v >> 12);
        float fj = (float)((v >> 6) & 63);
        float fk = (float)(v & 63);
        float s2 = fi*fi + fj*fj;
        float m0 = __fsqrt_rn(s2 + fk*fk);
        float m1 = __fsqrt_rn(s2 + (fk+1.0f)*(fk+1.0f));
        float m2 = __fsqrt_rn(s2 + (fk+2.0f)*(fk+2.0f));
        float m3 = __fsqrt_rn(s2 + (fk+3.0f)*(fk+3.0f));
        float m4 = __fsqrt_rn(s2 + (fk+4.0f)*(fk+4.0f));
        float m5 = __fsqrt_rn(s2 + (fk+5.0f)*(fk+5.0f));
        float m6 = __fsqrt_rn(s2 + (fk+6.0f)*(fk+6.0f));
        float m7 = __fsqrt_rn(s2 + (fk+7.0f)*(fk+7.0f));

        // row offset = bin*256 = byte<<8; h = hist + t (private column)
        h[(( bq.x        & 0xffu) << 8)] += xa.x * m0;
        h[(((bq.x >>  8) & 0xffu) << 8)] += xa.y * m1;
        h[(((bq.x >> 16) & 0xffu) << 8)] += xa.z * m2;
        h[(( bq.x >> 24         ) << 8)] += xa.w * m3;
        h[(( bq.y        & 0xffu) << 8)] += xb.x * m4;
        h[(((bq.y >>  8) & 0xffu) << 8)] += xb.y * m5;
        h[(((bq.y >> 16) & 0xffu) << 8)] += xb.z * m6;
        h[(( bq.y >> 24         ) << 8)] += xb.w * m7;
    }

    __syncthreads();

    // Flush: 8 warps; warp w handles bins {w, w+8, w+16, w+24}
    const int warp = t >> 5, lane = t & 31;
    const unsigned full = 0xffffffffu;
    for (int bin = warp; bin < NDENSE; bin += 8) {
        const float* row = &hist[bin * BTHREADS];
        float s = 0.0f;
        #pragma unroll
        for (int j = 0; j < 8; j++) s += row[lane + 32*j];
        #pragma unroll
        for (int d = 16; d; d >>= 1) s += __shfl_down_sync(full, s, d);
        if (lane == 0) atomicAdd(&g_scratch[pair * DSTRIDE + bin], s);
    }
}

// ---------------------------------------------------------------------------
// Kernel C: per-channel group norm. 32 blocks: 16 per channel; each block
// redundantly computes the (cheap) channel stats over the 1600 dense values,
// then writes a disjoint 1024-element output slice. Two-pass mean/var; zero
// bins enter the variance analytically as (16384 - 64*25) * mean^2.
// ---------------------------------------------------------------------------
#define CSEG 16                        // output segments per channel

__global__ __launch_bounds__(256) void gn_kernel(const float* __restrict__ gamma,
                                                 const float* __restrict__ beta,
                                                 float* __restrict__ out) {
    const int c   = blockIdx.x & 1;
    const int seg = blockIdx.x >> 1;
    const int t = threadIdx.x;
    const int lane = t & 31, warp = t >> 5;
    const unsigned full = 0xffffffffu;

    __shared__ float red[8];
    __shared__ float s_mean, s_rs;

    float vals[7];                      // ceil(1600/256) = 7 slots
    float sum = 0.0f;
    #pragma unroll
    for (int i = 0; i < 7; i++) {
        int idx = i * 256 + t;
        float g = 0.0f;
        if (idx < BB * NDENSE) {
            int b = idx / NDENSE, d = idx % NDENSE;
            g = g_scratch[(b * CC + c) * DSTRIDE + d];
        }
        vals[i] = g;
        sum += g;
    }
    #pragma unroll
    for (int d = 16; d; d >>= 1) sum += __shfl_down_sync(full, sum, d);
    if (lane == 0) red[warp] = sum;
    __syncthreads();
    if (t == 0) {
        float tot = 0.0f;
        #pragma unroll
        for (int w = 0; w < 8; w++) tot += red[w];
        s_mean = tot * (1.0f / (BB * NBIN * NBIN));
    }
    __syncthreads();
    float mean = s_mean;

    float vs = 0.0f;
    #pragma unroll
    for (int i = 0; i < 7; i++) {
        int idx = i * 256 + t;
        if (idx < BB * NDENSE) {
            float d = vals[i] - mean;
            vs = fmaf(d, d, vs);
        }
    }
    #pragma unroll
    for (int d = 16; d; d >>= 1) vs += __shfl_down_sync(full, vs, d);
    __syncthreads();
    if (lane == 0) red[warp] = vs;
    __syncthreads();
    if (t == 0) {
        float tot = 0.0f;
        #pragma unroll
        for (int w = 0; w < 8; w++) tot += red[w];
        tot += (float)(BB * NBIN * NBIN - BB * NDENSE) * s_mean * s_mean;
        float var = tot * (1.0f / (BB * NBIN * NBIN));
        s_rs = rsqrtf(var + EPSV);
    }
    __syncthreads();
    float rs = s_rs;
    float ga = gamma[c], be = beta[c];

    // this block writes outputs [seg*1024, (seg+1)*1024) of channel c
    {
        int idx = seg * 1024 + t;                 // 4 iters of 256
        #pragma unroll
        for (int i = 0; i < 4; i++, idx += 256) {
            int b = idx >> 8, s = idx & 255;
            int ax = s >> 4, az = s & 15;
            float g = 0.0f;
            if (ax < 5 && az < 5)
                g = g_scratch[(b * CC + c) * DSTRIDE + ax * 5 + az];
            out[(b * CC + c) * 256 + s] = (g - mean) * rs * ga + be;
        }
    }
}

// ---------------------------------------------------------------------------
extern "C" void kernel_launch(void* const* d_in, const int* in_sizes, int n_in,
                              void* d_out, int out_size) {
    const float* x     = (const float*)d_in[0];   // [64, 2*64^3]
    const float* gamma = (const float*)d_in[1];   // [2]
    const float* beta  = (const float*)d_in[2];   // [2]
    float* out = (float*)d_out;                   // [64,2,16,16] f32

    build_tables_kernel<<<NVOX / 4 / 256, 256>>>();
    accumulate_kernel<<<NPAIR * SPLIT, BTHREADS>>>(x);
    gn_kernel<<<CC * CSEG, 256>>>(gamma, beta, out);
}